// round 15
// baseline (speedup 1.0000x reference)
#include <cuda_runtime.h>
#include <math.h>

// FFM forward: B=16384, LATENT=16, F=6 fields.
// DIMS      = {1000000, 500000, 500000, 100000, 10000, 1000}
// SEQ_LENS  = [1, 1, 50, 20, 1, 1]
//
// Round 12: same structure as the 78.6us round-9 kernel. L2 residency hints
// re-expressed via createpolicy + ld.global.nc.L2::cache_hint (the scalar-
// compatible form; the bare .L2::evict_last modifier is vector-only on
// sm_103a ptxas).
//   evict_last : E3 (32MB table, 105MB requests), E4, E5, L2tab, L3tab
//   evict_first: E0/E1/E2 streams.

#define B_TOTAL 16384
#define LAT 16

__device__ __forceinline__ unsigned long long mk_policy_keep() {
    unsigned long long pol;
    asm("createpolicy.fractional.L2::evict_last.b64 %0, 1.0;" : "=l"(pol));
    return pol;
}
__device__ __forceinline__ unsigned long long mk_policy_stream() {
    unsigned long long pol;
    asm("createpolicy.fractional.L2::evict_first.b64 %0, 1.0;" : "=l"(pol));
    return pol;
}
__device__ __forceinline__ float ldg_pol(const float* p, unsigned long long pol) {
    float v;
    asm("ld.global.nc.L2::cache_hint.f32 %0, [%1], %2;"
        : "=f"(v) : "l"(p), "l"(pol));
    return v;
}

// POL_E/POL_L: 0 = streaming (evict_first), 1 = resident (evict_last)
template<int SEQ, long DIM, int UNR, int POL_E, int POL_L>
__device__ __forceinline__ void do_field(const int* __restrict__ xp,
                                         const float* __restrict__ E,
                                         const float* __restrict__ L,
                                         int lane, float wsc,
                                         unsigned long long pol_keep,
                                         unsigned long long pol_stream,
                                         float (&acc)[5], float& lin0, float& lin1)
{
    const unsigned long long pe = POL_E ? pol_keep : pol_stream;
    const unsigned long long pl = POL_L ? pol_keep : pol_stream;
#pragma unroll UNR
    for (int t = 0; t < SEQ; ++t) {
        const int tok = __ldg(xp + t);
        const float* e = E + (size_t)tok * LAT + lane;
        acc[0] += ldg_pol(e,                pe);
        acc[1] += ldg_pol(e + DIM * LAT,     pe);
        acc[2] += ldg_pol(e + DIM * LAT * 2, pe);
        acc[3] += ldg_pol(e + DIM * LAT * 3, pe);
        acc[4] += ldg_pol(e + DIM * LAT * 4, pe);
        // all 16 lanes same address -> single broadcast request
        const float lv = ldg_pol(L + tok, pl);
        if (t & 1) lin1 += lv * wsc;
        else       lin0 += lv * wsc;
    }
}

__global__ __launch_bounds__(128) void ffm_kernel(
    const int* __restrict__ x0, const int* __restrict__ x1, const int* __restrict__ x2,
    const int* __restrict__ x3, const int* __restrict__ x4, const int* __restrict__ x5,
    const float* __restrict__ E0, const float* __restrict__ E1, const float* __restrict__ E2,
    const float* __restrict__ E3, const float* __restrict__ E4, const float* __restrict__ E5,
    const float* __restrict__ L0, const float* __restrict__ L1, const float* __restrict__ L2,
    const float* __restrict__ L3, const float* __restrict__ L4, const float* __restrict__ L5,
    const float* __restrict__ Wd, const float* __restrict__ bd,
    float* __restrict__ out)
{
    const int tid  = blockIdx.x * blockDim.x + threadIdx.x;
    const int b    = tid >> 4;           // one batch element per 16 lanes
    const int lane = threadIdx.x & 15;   // lane = latent dim
    if (b >= B_TOTAL) return;

    const unsigned long long pol_keep   = mk_policy_keep();
    const unsigned long long pol_stream = mk_policy_stream();

    float a0[5] = {0,0,0,0,0};
    float a1[5] = {0,0,0,0,0};
    float a2[5] = {0,0,0,0,0};
    float a3[5] = {0,0,0,0,0};
    float a4[5] = {0,0,0,0,0};
    float a5[5] = {0,0,0,0,0};
    float lin0 = 0.f, lin1 = 0.f;

    const float w0 = __ldg(Wd + 0);
    const float w1 = __ldg(Wd + 1);
    const float w2 = __ldg(Wd + 2) * (1.0f / 50.0f);
    const float w3 = __ldg(Wd + 3) * (1.0f / 20.0f);
    const float w4 = __ldg(Wd + 4);
    const float w5 = __ldg(Wd + 5);

    // E0/E1/E2: streaming. E3/E4/E5 + L2tab/L3tab: L2-resident.
    do_field<1,  1000000, 1,  0, 0>(x0 + (size_t)b * 1,  E0, L0, lane, w0, pol_keep, pol_stream, a0, lin0, lin1);
    do_field<1,   500000, 1,  0, 0>(x1 + (size_t)b * 1,  E1, L1, lane, w1, pol_keep, pol_stream, a1, lin0, lin1);
    do_field<50,  500000, 10, 0, 1>(x2 + (size_t)b * 50, E2, L2, lane, w2, pol_keep, pol_stream, a2, lin0, lin1);
    do_field<20,  100000, 10, 1, 1>(x3 + (size_t)b * 20, E3, L3, lane, w3, pol_keep, pol_stream, a3, lin0, lin1);
    do_field<1,    10000, 1,  1, 1>(x4 + (size_t)b * 1,  E4, L4, lane, w4, pol_keep, pol_stream, a4, lin0, lin1);
    do_field<1,     1000, 1,  1, 1>(x5 + (size_t)b * 1,  E5, L5, lane, w5, pol_keep, pol_stream, a5, lin0, lin1);

    const float lin = lin0 + lin1;

    // means: fields 0,1,4,5 have seq=1 (no scale needed)
#pragma unroll
    for (int k = 0; k < 5; ++k) a2[k] *= (1.0f / 50.0f);
#pragma unroll
    for (int k = 0; k < 5; ++k) a3[k] *= (1.0f / 20.0f);

    // fm = sum over pairs (i<j) of acc_i[j-1] * acc_j[i]
    float fm = 0.f;
    fm += a0[0]*a1[0];  // (0,1)
    fm += a0[1]*a2[0];  // (0,2)
    fm += a0[2]*a3[0];  // (0,3)
    fm += a0[3]*a4[0];  // (0,4)
    fm += a0[4]*a5[0];  // (0,5)
    fm += a1[1]*a2[1];  // (1,2)
    fm += a1[2]*a3[1];  // (1,3)
    fm += a1[3]*a4[1];  // (1,4)
    fm += a1[4]*a5[1];  // (1,5)
    fm += a2[2]*a3[2];  // (2,3)
    fm += a2[3]*a4[2];  // (2,4)
    fm += a2[4]*a5[2];  // (2,5)
    fm += a3[3]*a4[3];  // (3,4)
    fm += a3[4]*a5[3];  // (3,5)
    fm += a4[4]*a5[4];  // (4,5)

    // reduce fm over the 16 latent lanes
    fm += __shfl_xor_sync(0xffffffffu, fm, 8, 16);
    fm += __shfl_xor_sync(0xffffffffu, fm, 4, 16);
    fm += __shfl_xor_sync(0xffffffffu, fm, 2, 16);
    fm += __shfl_xor_sync(0xffffffffu, fm, 1, 16);

    if (lane == 0) {
        float z = lin + __ldg(bd);
        z = z > 0.f ? z : 0.f;      // relu
        z += fm;
        out[b] = 1.0f / (1.0f + expf(-z));
    }
}

extern "C" void kernel_launch(void* const* d_in, const int* in_sizes, int n_in,
                              void* d_out, int out_size)
{
    static const long DIMS[6] = {1000000, 500000, 500000, 100000, 10000, 1000};

    const int*   x[6];
    const float* E[6];
    const float* L[6];

    for (int i = 0; i < 6; ++i) x[i] = (const int*)d_in[i];

    // Inputs 6..17 are E and L tables in field order; disambiguate by size:
    // E_i has 80*DIMS[i] elements, L_i has DIMS[i]. Disjoint sets.
    int ei = 0, li = 0;
    for (int i = 6; i < 18 && i < n_in; ++i) {
        long sz = (long)in_sizes[i];
        if (ei < 6 && sz == 80L * DIMS[ei]) {
            E[ei++] = (const float*)d_in[i];
        } else {
            L[li++] = (const float*)d_in[i];
        }
    }

    const float* Wd = (const float*)d_in[18];
    const float* bd = (const float*)d_in[19];

    const int threads = 128;                       // 8 elems/block
    const int blocks  = (B_TOTAL * 16) / threads;  // 2048 blocks

    ffm_kernel<<<blocks, threads>>>(
        x[0], x[1], x[2], x[3], x[4], x[5],
        E[0], E[1], E[2], E[3], E[4], E[5],
        L[0], L[1], L[2], L[3], L[4], L[5],
        Wd, bd, (float*)d_out);
}